// round 13
// baseline (speedup 1.0000x reference)
#include <cuda_runtime.h>

#define L 32768
#define E 1024
#define H 8
#define D 128
#define E4 256            // float4 per row
#define NB 256            // mega blocks (<=2/SM co-resident, 1 wave)
#define RPB 128           // rows per block in flash phase
#define TILE 8
#define NT (RPB/TILE)     // 16 tiles per block
#define RSQRT_D 0.08838834764831845f

typedef unsigned long long u64;

// ---------------- device scratch ----------------
__device__ float g_q[E];
__device__ float g_s[H][E];
__device__ float g_pm[NB * H];
__device__ float g_ps[NB * H];
__device__ float g_partial[NB][H][E];   // 8 MB (unnormalized, local max)
__device__ float g_partial2[32][H][E];  // 1 MB group partials
__device__ float g_w[H][E];
__device__ float g_attn[E];
__device__ unsigned g_ctr[8];           // grid-barrier counters (self-reset)

#define FMA2(d, a, b, c) \
    asm("fma.rn.f32x2 %0, %1, %2, %3;" : "=l"(d) : "l"(a), "l"(b), "l"(c))
#define ADD2(d, a, b) \
    asm("add.rn.f32x2 %0, %1, %2;" : "=l"(d) : "l"(a), "l"(b))

__device__ __forceinline__ u64 pack2(float a, float b) {
    u64 u; asm("mov.b64 %0, {%1, %2};" : "=l"(u) : "f"(a), "f"(b)); return u;
}
__device__ __forceinline__ float unpack_add(u64 u) {
    float lo, hi; asm("mov.b64 {%0, %1}, %2;" : "=f"(lo), "=f"(hi) : "l"(u));
    return lo + hi;
}
__device__ __forceinline__ float warp_sum(float v) {
    v += __shfl_xor_sync(0xffffffffu, v, 16);
    v += __shfl_xor_sync(0xffffffffu, v, 8);
    v += __shfl_xor_sync(0xffffffffu, v, 4);
    v += __shfl_xor_sync(0xffffffffu, v, 2);
    v += __shfl_xor_sync(0xffffffffu, v, 1);
    return v;
}
__device__ __forceinline__ float warp_max(float v) {
    v = fmaxf(v, __shfl_xor_sync(0xffffffffu, v, 16));
    v = fmaxf(v, __shfl_xor_sync(0xffffffffu, v, 8));
    v = fmaxf(v, __shfl_xor_sync(0xffffffffu, v, 4));
    v = fmaxf(v, __shfl_xor_sync(0xffffffffu, v, 2));
    v = fmaxf(v, __shfl_xor_sync(0xffffffffu, v, 1));
    return v;
}

// grid barrier: all NB blocks co-resident (verified occupancy), counter idx i.
__device__ __forceinline__ void gbar(int i, int tid) {
    __syncthreads();
    if (tid == 0) {
        __threadfence();
        atomicAdd(&g_ctr[i], 1u);
        while (((volatile unsigned*)g_ctr)[i] < NB) __nanosleep(64);
    }
    __syncthreads();
}

struct FSmem {
    float4 xbuf[3][TILE][E4];   // 96 KB triple-buffered X tile
    float plg[4][TILE][H];      // per-column-quarter partial logits
    u64   a2[TILE][H];          // packed exp weights
    float m_run[H], s_run[H], f_sh[H];
};

__device__ __forceinline__ void issue_loads(FSmem* s, int buf,
                                            const float4* __restrict__ X4,
                                            int row_base, int t) {
    #pragma unroll
    for (int i = 0; i < 8; i++) {
        int idx = t + 256 * i;                  // 0..2047
        int row = idx >> 8, col = idx & 255;
        unsigned sa = (unsigned)__cvta_generic_to_shared(&s->xbuf[buf][row][col]);
        const float4* g = X4 + (size_t)(row_base + row) * E4 + col;
        asm volatile("cp.async.cg.shared.global [%0], [%1], 16;"
                     :: "r"(sa), "l"(g) : "memory");
    }
    asm volatile("cp.async.commit_group;" ::: "memory");
}

__global__ __launch_bounds__(256, 2) void k_mega(
        const float4* __restrict__ X4,
        const float4* __restrict__ Win4,
        const float*  __restrict__ bin,
        const float4* __restrict__ Wo4,
        const float*  __restrict__ bo,
        float* __restrict__ out) {
    extern __shared__ char smem_raw[];
    FSmem* s = reinterpret_cast<FSmem*>(smem_raw);
    float* red = (float*)smem_raw;              // scratch overlay (pre-flash)
    int t = threadIdx.x, w = t >> 5, j = t & 31;
    int b = blockIdx.x;

    // ============ phase Q: q = Wq·x0 + bq (blocks 0..127) ============
    if (b < 128) {
        int row = b * 8 + w;
        const float4* wr = Win4 + (size_t)row * E4;
        float4 a = make_float4(0.f, 0.f, 0.f, 0.f);
        #pragma unroll
        for (int i = 0; i < 8; i++) {
            float4 ww = wr[j + 32 * i];
            float4 x = X4[j + 32 * i];
            a.x = fmaf(ww.x, x.x, a.x); a.y = fmaf(ww.y, x.y, a.y);
            a.z = fmaf(ww.z, x.z, a.z); a.w = fmaf(ww.w, x.w, a.w);
        }
        float acc = warp_sum((a.x + a.y) + (a.z + a.w));
        if (j == 0) g_q[row] = acc + bin[row];
    }
    gbar(0, t);

    // ============ phase S: s[h] = rsqrtD * Wk_h^T q_h (blocks 0..127) ====
    if (b < 128) {
        int h = b >> 4, seg = b & 15;
        int dgrp = t >> 4, ec = t & 15;
        int e4 = seg * 16 + ec;
        float* qsh = red;                       // [128]
        float4* pacc = (float4*)(red + 128);    // [16][16]
        if (t < D) qsh[t] = __ldcg(&g_q[h * D + t]);
        __syncthreads();
        const float4* Wk = Win4 + (size_t)(E + h * D + dgrp * 8) * E4 + e4;
        float4 a = make_float4(0.f, 0.f, 0.f, 0.f);
        #pragma unroll
        for (int d = 0; d < 8; d++) {
            float4 ww = Wk[(size_t)d * E4];
            float q = qsh[dgrp * 8 + d];
            a.x = fmaf(ww.x, q, a.x); a.y = fmaf(ww.y, q, a.y);
            a.z = fmaf(ww.z, q, a.z); a.w = fmaf(ww.w, q, a.w);
        }
        pacc[dgrp * 16 + ec] = a;
        __syncthreads();
        if (t < 16) {
            float4 r = pacc[t];
            #pragma unroll
            for (int k = 1; k < 16; k++) {
                float4 v = pacc[k * 16 + t];
                r.x += v.x; r.y += v.y; r.z += v.z; r.w += v.w;
            }
            r.x *= RSQRT_D; r.y *= RSQRT_D; r.z *= RSQRT_D; r.w *= RSQRT_D;
            ((float4*)g_s[h])[seg * 16 + t] = r;
        }
    }
    gbar(1, t);

    // ============ phase F: fused logits + online softmax + weighted sum ==
    {
        int row0 = b * RPB;
        int hh = w >> 2, cq = w & 3;

        ulonglong2 sreg[2][4];                  // [fi][head k]
        #pragma unroll
        for (int fi = 0; fi < 2; fi++) {
            int f = cq * 64 + fi * 32 + j;
            #pragma unroll
            for (int k = 0; k < 4; k++) {
                float4 sv = __ldcg(((const float4*)g_s[hh * 4 + k]) + f);
                sreg[fi][k] = *(ulonglong2*)&sv;
            }
        }
        __syncthreads();                        // red overlay dead before FSmem use
        if (t < H) { s->m_run[t] = -1e30f; s->s_run[t] = 0.f; }

        u64 accB[H][2];
        #pragma unroll
        for (int h = 0; h < H; h++) { accB[h][0] = 0ull; accB[h][1] = 0ull; }

        issue_loads(s, 0, X4, row0, t);
        issue_loads(s, 1, X4, row0 + TILE, t);

        for (int tile = 0; tile < NT; tile++) {
            int buf = tile % 3;
            if (tile < NT - 1)
                asm volatile("cp.async.wait_group 1;" ::: "memory");
            else
                asm volatile("cp.async.wait_group 0;" ::: "memory");
            __syncthreads();
            if (tile + 2 < NT)
                issue_loads(s, (tile + 2) % 3, X4, row0 + (tile + 2) * TILE, t);

            // ---- phase A: packed FMA2 + butterfly reduce-scatter ----
            #pragma unroll
            for (int hr = 0; hr < 2; hr++) {
                u64 cur[16];                    // i = rr*4 + k
                #pragma unroll
                for (int i = 0; i < 16; i++) cur[i] = 0ull;
                #pragma unroll
                for (int fi = 0; fi < 2; fi++) {
                    int f = cq * 64 + fi * 32 + j;
                    #pragma unroll
                    for (int rr = 0; rr < 4; rr++) {
                        float4 xv = s->xbuf[buf][hr * 4 + rr][f];
                        ulonglong2 xp = *(ulonglong2*)&xv;
                        #pragma unroll
                        for (int k = 0; k < 4; k++) {
                            FMA2(cur[rr * 4 + k], xp.x, sreg[fi][k].x, cur[rr * 4 + k]);
                            FMA2(cur[rr * 4 + k], xp.y, sreg[fi][k].y, cur[rr * 4 + k]);
                        }
                    }
                }
                // butterfly: 16 u64 sums -> 1 complete sum per lane-pair
                bool b16 = (j & 16);
                u64 n8[8];
                #pragma unroll
                for (int m = 0; m < 8; m++) {
                    u64 snd = b16 ? cur[m] : cur[m + 8];
                    u64 kp  = b16 ? cur[m + 8] : cur[m];
                    u64 rc = __shfl_xor_sync(0xffffffffu, snd, 16);
                    ADD2(n8[m], kp, rc);
                }
                bool b8 = (j & 8);
                u64 n4[4];
                #pragma unroll
                for (int m = 0; m < 4; m++) {
                    u64 snd = b8 ? n8[m] : n8[m + 4];
                    u64 kp  = b8 ? n8[m + 4] : n8[m];
                    u64 rc = __shfl_xor_sync(0xffffffffu, snd, 8);
                    ADD2(n4[m], kp, rc);
                }
                bool b4 = (j & 4);
                u64 n2[2];
                #pragma unroll
                for (int m = 0; m < 2; m++) {
                    u64 snd = b4 ? n4[m] : n4[m + 2];
                    u64 kp  = b4 ? n4[m + 2] : n4[m];
                    u64 rc = __shfl_xor_sync(0xffffffffu, snd, 4);
                    ADD2(n2[m], kp, rc);
                }
                bool b2 = (j & 2);
                u64 snd = b2 ? n2[0] : n2[1];
                u64 kp  = b2 ? n2[1] : n2[0];
                u64 rc = __shfl_xor_sync(0xffffffffu, snd, 2);
                u64 n1; ADD2(n1, kp, rc);
                rc = __shfl_xor_sync(0xffffffffu, n1, 1);
                ADD2(n1, n1, rc);
                float z = unpack_add(n1);
                int idx = ((j >> 4) & 1) * 8 + ((j >> 3) & 1) * 4
                        + ((j >> 2) & 1) * 2 + ((j >> 1) & 1);
                if (!(j & 1))
                    s->plg[cq][hr * 4 + (idx >> 2)][hh * 4 + (idx & 3)] = z;
            }
            __syncthreads();

            // ---- stats: 64-thread warp-parallel online softmax ----
            int pred = 1;
            if (t < 64) {
                int h = t >> 3, r = t & 7;
                float z = s->plg[0][r][h] + s->plg[1][r][h]
                        + s->plg[2][r][h] + s->plg[3][r][h];
                float mt = z;
                mt = fmaxf(mt, __shfl_xor_sync(0xffffffffu, mt, 4));
                mt = fmaxf(mt, __shfl_xor_sync(0xffffffffu, mt, 2));
                mt = fmaxf(mt, __shfl_xor_sync(0xffffffffu, mt, 1));
                float m_old = s->m_run[h];
                float m_new = fmaxf(m_old, mt);
                float e = __expf(z - m_new);
                s->a2[r][h] = pack2(e, e);
                float st = e;
                st += __shfl_xor_sync(0xffffffffu, st, 4);
                st += __shfl_xor_sync(0xffffffffu, st, 2);
                st += __shfl_xor_sync(0xffffffffu, st, 1);
                if (r == 0) {
                    float fr = __expf(m_old - m_new);
                    s->s_run[h] = s->s_run[h] * fr + st;
                    s->m_run[h] = m_new;
                    s->f_sh[h] = fr;
                    pred = (fr == 1.0f);
                }
            }
            int all_one = __syncthreads_and(pred);

            // ---- phase B: rescale (only if some max moved) + accumulate ----
            if (!all_one) {
                #pragma unroll
                for (int h = 0; h < H; h++) {
                    float fh = s->f_sh[h];
                    u64 f2 = pack2(fh, fh);
                    FMA2(accB[h][0], accB[h][0], f2, 0ull);
                    FMA2(accB[h][1], accB[h][1], f2, 0ull);
                }
            }
            #pragma unroll
            for (int r = 0; r < TILE; r++) {
                ulonglong2 xv = *(const ulonglong2*)&s->xbuf[buf][r][t];
                const ulonglong2* ap = (const ulonglong2*)s->a2[r];
                #pragma unroll
                for (int hq = 0; hq < 4; hq++) {
                    ulonglong2 aa = ap[hq];
                    FMA2(accB[2 * hq][0],     aa.x, xv.x, accB[2 * hq][0]);
                    FMA2(accB[2 * hq][1],     aa.x, xv.y, accB[2 * hq][1]);
                    FMA2(accB[2 * hq + 1][0], aa.y, xv.x, accB[2 * hq + 1][0]);
                    FMA2(accB[2 * hq + 1][1], aa.y, xv.y, accB[2 * hq + 1][1]);
                }
            }
        }

        #pragma unroll
        for (int h = 0; h < H; h++) {
            ulonglong2 v; v.x = accB[h][0]; v.y = accB[h][1];
            ((ulonglong2*)g_partial[b][h])[t] = v;
        }
        if (t < H) { g_pm[b * H + t] = s->m_run[t]; g_ps[b * H + t] = s->s_run[t]; }
    }
    gbar(2, t);

    // ============ phase R1: rescaled 8-slot group reduce =================
    {
        int g = b >> 3, h = b & 7;
        int out4 = h * 256 + t;
        float pmv = __ldcg(&g_pm[t * H + h]);   // t covers all 256 slots
        float m = warp_max(pmv);
        if (j == 0) red[w] = m;
        __syncthreads();
        if (t == 0) {
            float mm = red[0];
            #pragma unroll
            for (int k = 1; k < 8; k++) mm = fmaxf(mm, red[k]);
            red[8] = mm;
        }
        __syncthreads();
        float M = red[8];
        const float4* P = (const float4*)g_partial;
        float4 acc = make_float4(0.f, 0.f, 0.f, 0.f);
        #pragma unroll
        for (int k = 0; k < 8; k++) {
            int sl = g * 8 + k;
            float f = __expf(__ldcg(&g_pm[sl * H + h]) - M);
            float4 v = __ldcg(P + (size_t)sl * 2048 + out4);
            acc.x = fmaf(v.x, f, acc.x); acc.y = fmaf(v.y, f, acc.y);
            acc.z = fmaf(v.z, f, acc.z); acc.w = fmaf(v.w, f, acc.w);
        }
        ((float4*)g_partial2)[(size_t)g * 2048 + out4] = acc;
    }
    gbar(3, t);

    // ============ phase R2: final sum + normalize (blocks 0..7) ==========
    if (b < 8) {
        int h = b;
        int out4 = h * 256 + t;
        float pmv = __ldcg(&g_pm[t * H + h]);
        float m = warp_max(pmv);
        if (j == 0) red[w] = m;
        __syncthreads();
        if (t == 0) {
            float mm = red[0];
            #pragma unroll
            for (int k = 1; k < 8; k++) mm = fmaxf(mm, red[k]);
            red[8] = mm;
        }
        __syncthreads();
        float M = red[8];
        float sp = __ldcg(&g_ps[t * H + h]) * __expf(pmv - M);
        sp = warp_sum(sp);
        if (j == 0) red[16 + w] = sp;
        __syncthreads();
        if (t == 0) {
            float ss = 0.f;
            #pragma unroll
            for (int k = 0; k < 8; k++) ss += red[16 + k];
            red[9] = 1.0f / ss;
        }
        __syncthreads();
        float invS = red[9];
        const float4* P2 = (const float4*)g_partial2;
        float4 acc = make_float4(0.f, 0.f, 0.f, 0.f);
        #pragma unroll
        for (int g = 0; g < 32; g++) {
            float4 v = __ldcg(P2 + (size_t)g * 2048 + out4);
            acc.x += v.x; acc.y += v.y; acc.z += v.z; acc.w += v.w;
        }
        acc.x *= invS; acc.y *= invS; acc.z *= invS; acc.w *= invS;
        ((float4*)g_w)[out4] = acc;
    }
    gbar(4, t);

    // ============ phase V: attn = Wv·w + bv (blocks 0..127) ==============
    if (b < 128) {
        int row = b * 8 + w;
        int h = row >> 7;
        const float4* wr = Win4 + (size_t)(2 * E + row) * E4;
        const float4* v4 = (const float4*)g_w[h];
        float4 a = make_float4(0.f, 0.f, 0.f, 0.f);
        #pragma unroll
        for (int i = 0; i < 8; i++) {
            float4 ww = wr[j + 32 * i];
            float4 x = __ldcg(v4 + j + 32 * i);
            a.x = fmaf(ww.x, x.x, a.x); a.y = fmaf(ww.y, x.y, a.y);
            a.z = fmaf(ww.z, x.z, a.z); a.w = fmaf(ww.w, x.w, a.w);
        }
        float acc = warp_sum((a.x + a.y) + (a.z + a.w));
        if (j == 0) g_attn[row] = acc + bin[2 * E + row];
    }
    gbar(5, t);

    // ============ phase O: out = Wo·attn + bo (blocks 0..127) ============
    if (b < 128) {
        int row = b * 8 + w;
        const float4* wr = Wo4 + (size_t)row * E4;
        const float4* v4 = (const float4*)g_attn;
        float4 a = make_float4(0.f, 0.f, 0.f, 0.f);
        #pragma unroll
        for (int i = 0; i < 8; i++) {
            float4 ww = wr[j + 32 * i];
            float4 x = __ldcg(v4 + j + 32 * i);
            a.x = fmaf(ww.x, x.x, a.x); a.y = fmaf(ww.y, x.y, a.y);
            a.z = fmaf(ww.z, x.z, a.z); a.w = fmaf(ww.w, x.w, a.w);
        }
        float acc = warp_sum((a.x + a.y) + (a.z + a.w));
        if (j == 0) out[row] = acc + bo[row];
    }

    // ============ counter self-reset (last finisher) =====================
    __syncthreads();
    if (t == 0) {
        __threadfence();
        if (atomicAdd(&g_ctr[6], 1u) == NB - 1) {
            #pragma unroll
            for (int i = 0; i < 7; i++) g_ctr[i] = 0;
            __threadfence();
        }
    }
}

extern "C" void kernel_launch(void* const* d_in, const int* in_sizes, int n_in,
                              void* d_out, int out_size) {
    const float* x   = (const float*)d_in[0];   // [L, E]
    const float* Win = (const float*)d_in[1];   // [3E, E]
    const float* bin = (const float*)d_in[2];   // [3E]
    const float* Wo  = (const float*)d_in[3];   // [E, E]
    const float* bo  = (const float*)d_in[4];   // [E]
    float* out = (float*)d_out;

    cudaFuncSetAttribute(k_mega, cudaFuncAttributeMaxDynamicSharedMemorySize,
                         (int)sizeof(FSmem));

    k_mega<<<NB, 256, sizeof(FSmem)>>>((const float4*)x, (const float4*)Win,
                                       bin, (const float4*)Wo, bo, out);
}

// round 15
// speedup vs baseline: 1.1062x; 1.1062x over previous
#include <cuda_runtime.h>

#define L 32768
#define E 1024
#define H 8
#define D 128
#define E4 256            // float4 per row
#define NB 256            // mega blocks (<=2/SM co-resident, 1 wave)
#define RPB 128           // rows per block in flash phase
#define TILE 8
#define NT (RPB/TILE)     // 16 tiles per block
#define RSQRT_D 0.08838834764831845f

typedef unsigned long long u64;

// ---------------- device scratch ----------------
__device__ float g_q[E];
__device__ float g_s[H][E];
__device__ float g_pm[NB * H];
__device__ float g_ps[NB * H];
__device__ float g_partial[NB][H][E];   // 8 MB (unnormalized, local max)
__device__ float g_partial2[32][H][E];  // 1 MB group partials
__device__ float g_w[H][E];
__device__ float g_attn[E];
__device__ unsigned g_ctr[8];           // grid-barrier counters (self-reset)

#define FMA2(d, a, b, c) \
    asm("fma.rn.f32x2 %0, %1, %2, %3;" : "=l"(d) : "l"(a), "l"(b), "l"(c))
#define ADD2(d, a, b) \
    asm("add.rn.f32x2 %0, %1, %2;" : "=l"(d) : "l"(a), "l"(b))

__device__ __forceinline__ u64 pack2(float a, float b) {
    u64 u; asm("mov.b64 %0, {%1, %2};" : "=l"(u) : "f"(a), "f"(b)); return u;
}
__device__ __forceinline__ float unpack_add(u64 u) {
    float lo, hi; asm("mov.b64 {%0, %1}, %2;" : "=f"(lo), "=f"(hi) : "l"(u));
    return lo + hi;
}
__device__ __forceinline__ float warp_sum(float v) {
    v += __shfl_xor_sync(0xffffffffu, v, 16);
    v += __shfl_xor_sync(0xffffffffu, v, 8);
    v += __shfl_xor_sync(0xffffffffu, v, 4);
    v += __shfl_xor_sync(0xffffffffu, v, 2);
    v += __shfl_xor_sync(0xffffffffu, v, 1);
    return v;
}
__device__ __forceinline__ float warp_max(float v) {
    v = fmaxf(v, __shfl_xor_sync(0xffffffffu, v, 16));
    v = fmaxf(v, __shfl_xor_sync(0xffffffffu, v, 8));
    v = fmaxf(v, __shfl_xor_sync(0xffffffffu, v, 4));
    v = fmaxf(v, __shfl_xor_sync(0xffffffffu, v, 2));
    v = fmaxf(v, __shfl_xor_sync(0xffffffffu, v, 1));
    return v;
}

// grid barrier: all NB blocks co-resident (verified occupancy), counter idx i.
__device__ __forceinline__ void gbar(int i, int tid) {
    __syncthreads();
    if (tid == 0) {
        __threadfence();
        atomicAdd(&g_ctr[i], 1u);
        while (((volatile unsigned*)g_ctr)[i] < NB) __nanosleep(128);
    }
    __syncthreads();
}

struct FSmem {
    float4 xbuf[2][TILE][E4];   // 64 KB double-buffered X tile
    float plg[4][TILE][H];      // per-column-quarter partial logits
    u64   a2[TILE][H];          // packed exp weights
    float m_run[H], s_run[H], f_sh[H];
};

__device__ __forceinline__ void issue_loads(FSmem* s, int buf,
                                            const float4* __restrict__ X4,
                                            int row_base, int t) {
    #pragma unroll
    for (int i = 0; i < 8; i++) {
        int idx = t + 256 * i;                  // 0..2047
        int row = idx >> 8, col = idx & 255;
        unsigned sa = (unsigned)__cvta_generic_to_shared(&s->xbuf[buf][row][col]);
        const float4* g = X4 + (size_t)(row_base + row) * E4 + col;
        asm volatile("cp.async.cg.shared.global [%0], [%1], 16;"
                     :: "r"(sa), "l"(g) : "memory");
    }
    asm volatile("cp.async.commit_group;" ::: "memory");
}

// one flash tile; buf passed as a literal so all SMEM offsets fold to constants
__device__ __forceinline__ void flash_tile(
        FSmem* s, const int buf, int tile, int row0,
        const float4* __restrict__ X4,
        int t, int j, int hh, int cq,
        ulonglong2 (&sreg)[2][4], u64 (&accB)[H][2]) {
    asm volatile("cp.async.wait_group 0;" ::: "memory");
    __syncthreads();
    if (tile + 1 < NT) issue_loads(s, buf ^ 1, X4, row0 + (tile + 1) * TILE, t);

    // ---- phase A: packed FMA2 + butterfly reduce-scatter ----
    #pragma unroll
    for (int hr = 0; hr < 2; hr++) {
        u64 cur[16];                    // i = rr*4 + k
        #pragma unroll
        for (int i = 0; i < 16; i++) cur[i] = 0ull;
        #pragma unroll
        for (int fi = 0; fi < 2; fi++) {
            int f = cq * 64 + fi * 32 + j;
            #pragma unroll
            for (int rr = 0; rr < 4; rr++) {
                float4 xv = s->xbuf[buf][hr * 4 + rr][f];
                ulonglong2 xp = *(ulonglong2*)&xv;
                #pragma unroll
                for (int k = 0; k < 4; k++) {
                    FMA2(cur[rr * 4 + k], xp.x, sreg[fi][k].x, cur[rr * 4 + k]);
                    FMA2(cur[rr * 4 + k], xp.y, sreg[fi][k].y, cur[rr * 4 + k]);
                }
            }
        }
        // butterfly: 16 u64 sums -> 1 complete sum per lane-pair
        bool b16 = (j & 16);
        u64 n8[8];
        #pragma unroll
        for (int m = 0; m < 8; m++) {
            u64 snd = b16 ? cur[m] : cur[m + 8];
            u64 kp  = b16 ? cur[m + 8] : cur[m];
            u64 rc = __shfl_xor_sync(0xffffffffu, snd, 16);
            ADD2(n8[m], kp, rc);
        }
        bool b8 = (j & 8);
        u64 n4[4];
        #pragma unroll
        for (int m = 0; m < 4; m++) {
            u64 snd = b8 ? n8[m] : n8[m + 4];
            u64 kp  = b8 ? n8[m + 4] : n8[m];
            u64 rc = __shfl_xor_sync(0xffffffffu, snd, 8);
            ADD2(n4[m], kp, rc);
        }
        bool b4 = (j & 4);
        u64 n2[2];
        #pragma unroll
        for (int m = 0; m < 2; m++) {
            u64 snd = b4 ? n4[m] : n4[m + 2];
            u64 kp  = b4 ? n4[m + 2] : n4[m];
            u64 rc = __shfl_xor_sync(0xffffffffu, snd, 4);
            ADD2(n2[m], kp, rc);
        }
        bool b2 = (j & 2);
        u64 snd = b2 ? n2[0] : n2[1];
        u64 kp  = b2 ? n2[1] : n2[0];
        u64 rc = __shfl_xor_sync(0xffffffffu, snd, 2);
        u64 n1; ADD2(n1, kp, rc);
        rc = __shfl_xor_sync(0xffffffffu, n1, 1);
        ADD2(n1, n1, rc);
        float z = unpack_add(n1);
        int idx = ((j >> 4) & 1) * 8 + ((j >> 3) & 1) * 4
                + ((j >> 2) & 1) * 2 + ((j >> 1) & 1);
        if (!(j & 1))
            s->plg[cq][hr * 4 + (idx >> 2)][hh * 4 + (idx & 3)] = z;
    }
    __syncthreads();

    // ---- stats: 64-thread warp-parallel online softmax ----
    if (t < 64) {
        int h = t >> 3, r = t & 7;
        float z = s->plg[0][r][h] + s->plg[1][r][h]
                + s->plg[2][r][h] + s->plg[3][r][h];
        float mt = z;
        mt = fmaxf(mt, __shfl_xor_sync(0xffffffffu, mt, 4));
        mt = fmaxf(mt, __shfl_xor_sync(0xffffffffu, mt, 2));
        mt = fmaxf(mt, __shfl_xor_sync(0xffffffffu, mt, 1));
        float m_old = s->m_run[h];
        float m_new = fmaxf(m_old, mt);
        float e = __expf(z - m_new);
        s->a2[r][h] = pack2(e, e);
        float st = e;
        st += __shfl_xor_sync(0xffffffffu, st, 4);
        st += __shfl_xor_sync(0xffffffffu, st, 2);
        st += __shfl_xor_sync(0xffffffffu, st, 1);
        if (r == 0) {
            float fr = __expf(m_old - m_new);
            s->s_run[h] = s->s_run[h] * fr + st;
            s->m_run[h] = m_new;
            s->f_sh[h] = fr;
        }
    }
    __syncthreads();

    // ---- phase B: rescale + accumulate; thread t = column float4 t ----
    #pragma unroll
    for (int h = 0; h < H; h++) {
        float fh = s->f_sh[h];
        u64 f2 = pack2(fh, fh);
        FMA2(accB[h][0], accB[h][0], f2, 0ull);
        FMA2(accB[h][1], accB[h][1], f2, 0ull);
    }
    #pragma unroll
    for (int r = 0; r < TILE; r++) {
        ulonglong2 xv = *(const ulonglong2*)&s->xbuf[buf][r][t];
        const ulonglong2* ap = (const ulonglong2*)s->a2[r];
        #pragma unroll
        for (int hq = 0; hq < 4; hq++) {
            ulonglong2 aa = ap[hq];
            FMA2(accB[2 * hq][0],     aa.x, xv.x, accB[2 * hq][0]);
            FMA2(accB[2 * hq][1],     aa.x, xv.y, accB[2 * hq][1]);
            FMA2(accB[2 * hq + 1][0], aa.y, xv.x, accB[2 * hq + 1][0]);
            FMA2(accB[2 * hq + 1][1], aa.y, xv.y, accB[2 * hq + 1][1]);
        }
    }
}

__global__ __launch_bounds__(256, 2) void k_mega(
        const float4* __restrict__ X4,
        const float4* __restrict__ Win4,
        const float*  __restrict__ bin,
        const float4* __restrict__ Wo4,
        const float*  __restrict__ bo,
        float* __restrict__ out) {
    extern __shared__ char smem_raw[];
    FSmem* s = reinterpret_cast<FSmem*>(smem_raw);
    float* red = (float*)smem_raw;              // scratch overlay (pre-flash)
    int t = threadIdx.x, w = t >> 5, j = t & 31;
    int b = blockIdx.x;

    // ============ phase Q: q = Wq·x0 + bq (blocks 0..127) ============
    if (b < 128) {
        int row = b * 8 + w;
        const float4* wr = Win4 + (size_t)row * E4;
        float4 a = make_float4(0.f, 0.f, 0.f, 0.f);
        #pragma unroll
        for (int i = 0; i < 8; i++) {
            float4 ww = wr[j + 32 * i];
            float4 x = X4[j + 32 * i];
            a.x = fmaf(ww.x, x.x, a.x); a.y = fmaf(ww.y, x.y, a.y);
            a.z = fmaf(ww.z, x.z, a.z); a.w = fmaf(ww.w, x.w, a.w);
        }
        float acc = warp_sum((a.x + a.y) + (a.z + a.w));
        if (j == 0) g_q[row] = acc + bin[row];
    }
    gbar(0, t);

    // ============ phase S: s[h] = rsqrtD * Wk_h^T q_h (blocks 0..127) ====
    if (b < 128) {
        int h = b >> 4, seg = b & 15;
        int dgrp = t >> 4, ec = t & 15;
        int e4 = seg * 16 + ec;
        float* qsh = red;                       // [128]
        float4* pacc = (float4*)(red + 128);    // [16][16]
        if (t < D) qsh[t] = __ldcg(&g_q[h * D + t]);
        __syncthreads();
        const float4* Wk = Win4 + (size_t)(E + h * D + dgrp * 8) * E4 + e4;
        float4 a = make_float4(0.f, 0.f, 0.f, 0.f);
        #pragma unroll
        for (int d = 0; d < 8; d++) {
            float4 ww = Wk[(size_t)d * E4];
            float q = qsh[dgrp * 8 + d];
            a.x = fmaf(ww.x, q, a.x); a.y = fmaf(ww.y, q, a.y);
            a.z = fmaf(ww.z, q, a.z); a.w = fmaf(ww.w, q, a.w);
        }
        pacc[dgrp * 16 + ec] = a;
        __syncthreads();
        if (t < 16) {
            float4 r = pacc[t];
            #pragma unroll
            for (int k = 1; k < 16; k++) {
                float4 v = pacc[k * 16 + t];
                r.x += v.x; r.y += v.y; r.z += v.z; r.w += v.w;
            }
            r.x *= RSQRT_D; r.y *= RSQRT_D; r.z *= RSQRT_D; r.w *= RSQRT_D;
            ((float4*)g_s[h])[seg * 16 + t] = r;
        }
    }
    gbar(1, t);

    // ============ phase F: fused logits + online softmax + weighted sum ==
    {
        int row0 = b * RPB;
        int hh = w >> 2, cq = w & 3;

        ulonglong2 sreg[2][4];                  // [fi][head k]
        #pragma unroll
        for (int fi = 0; fi < 2; fi++) {
            int f = cq * 64 + fi * 32 + j;
            #pragma unroll
            for (int k = 0; k < 4; k++) {
                float4 sv = __ldcg(((const float4*)g_s[hh * 4 + k]) + f);
                sreg[fi][k] = *(ulonglong2*)&sv;
            }
        }
        __syncthreads();                        // red overlay dead before FSmem use
        if (t < H) { s->m_run[t] = -1e30f; s->s_run[t] = 0.f; }

        u64 accB[H][2];
        #pragma unroll
        for (int h = 0; h < H; h++) { accB[h][0] = 0ull; accB[h][1] = 0ull; }

        issue_loads(s, 0, X4, row0, t);

        // tile loop unrolled x2: buffer index is a literal in each half
        for (int tp = 0; tp < NT; tp += 2) {
            flash_tile(s, 0, tp,     row0, X4, t, j, hh, cq, sreg, accB);
            flash_tile(s, 1, tp + 1, row0, X4, t, j, hh, cq, sreg, accB);
        }

        #pragma unroll
        for (int h = 0; h < H; h++) {
            ulonglong2 v; v.x = accB[h][0]; v.y = accB[h][1];
            ((ulonglong2*)g_partial[b][h])[t] = v;
        }
        if (t < H) { g_pm[b * H + t] = s->m_run[t]; g_ps[b * H + t] = s->s_run[t]; }
    }
    gbar(2, t);

    // ============ phase R1: rescaled 8-slot group reduce =================
    {
        int g = b >> 3, h = b & 7;
        int out4 = h * 256 + t;
        float pmv = __ldcg(&g_pm[t * H + h]);   // t covers all 256 slots
        float m = warp_max(pmv);
        if (j == 0) red[w] = m;
        __syncthreads();
        if (t == 0) {
            float mm = red[0];
            #pragma unroll
            for (int k = 1; k < 8; k++) mm = fmaxf(mm, red[k]);
            red[8] = mm;
        }
        __syncthreads();
        float M = red[8];
        const float4* P = (const float4*)g_partial;
        float4 acc = make_float4(0.f, 0.f, 0.f, 0.f);
        #pragma unroll
        for (int k = 0; k < 8; k++) {
            int sl = g * 8 + k;
            float f = __expf(__ldcg(&g_pm[sl * H + h]) - M);
            float4 v = __ldcg(P + (size_t)sl * 2048 + out4);
            acc.x = fmaf(v.x, f, acc.x); acc.y = fmaf(v.y, f, acc.y);
            acc.z = fmaf(v.z, f, acc.z); acc.w = fmaf(v.w, f, acc.w);
        }
        ((float4*)g_partial2)[(size_t)g * 2048 + out4] = acc;
    }
    gbar(3, t);

    // ============ phase R2: final sum + normalize (blocks 0..7) ==========
    if (b < 8) {
        int h = b;
        int out4 = h * 256 + t;
        float pmv = __ldcg(&g_pm[t * H + h]);
        float m = warp_max(pmv);
        if (j == 0) red[w] = m;
        __syncthreads();
        if (t == 0) {
            float mm = red[0];
            #pragma unroll
            for (int k = 1; k < 8; k++) mm = fmaxf(mm, red[k]);
            red[8] = mm;
        }
        __syncthreads();
        float M = red[8];
        float sp = __ldcg(&g_ps[t * H + h]) * __expf(pmv - M);
        sp = warp_sum(sp);
        if (j == 0) red[16 + w] = sp;
        __syncthreads();
        if (t == 0) {
            float ss = 0.f;
            #pragma unroll
            for (int k = 0; k < 8; k++) ss += red[16 + k];
            red[9] = 1.0f / ss;
        }
        __syncthreads();
        float invS = red[9];
        const float4* P2 = (const float4*)g_partial2;
        float4 acc = make_float4(0.f, 0.f, 0.f, 0.f);
        #pragma unroll
        for (int g = 0; g < 32; g++) {
            float4 v = __ldcg(P2 + (size_t)g * 2048 + out4);
            acc.x += v.x; acc.y += v.y; acc.z += v.z; acc.w += v.w;
        }
        acc.x *= invS; acc.y *= invS; acc.z *= invS; acc.w *= invS;
        ((float4*)g_w)[out4] = acc;
    }
    gbar(4, t);

    // ============ phase V: attn = Wv·w + bv (blocks 0..127) ==============
    if (b < 128) {
        int row = b * 8 + w;
        int h = row >> 7;
        const float4* wr = Win4 + (size_t)(2 * E + row) * E4;
        const float4* v4 = (const float4*)g_w[h];
        float4 a = make_float4(0.f, 0.f, 0.f, 0.f);
        #pragma unroll
        for (int i = 0; i < 8; i++) {
            float4 ww = wr[j + 32 * i];
            float4 x = __ldcg(v4 + j + 32 * i);
            a.x = fmaf(ww.x, x.x, a.x); a.y = fmaf(ww.y, x.y, a.y);
            a.z = fmaf(ww.z, x.z, a.z); a.w = fmaf(ww.w, x.w, a.w);
        }
        float acc = warp_sum((a.x + a.y) + (a.z + a.w));
        if (j == 0) g_attn[row] = acc + bin[2 * E + row];
    }
    gbar(5, t);

    // ============ phase O: out = Wo·attn + bo (blocks 0..127) ============
    if (b < 128) {
        int row = b * 8 + w;
        const float4* wr = Wo4 + (size_t)row * E4;
        const float4* v4 = (const float4*)g_attn;
        float4 a = make_float4(0.f, 0.f, 0.f, 0.f);
        #pragma unroll
        for (int i = 0; i < 8; i++) {
            float4 ww = wr[j + 32 * i];
            float4 x = __ldcg(v4 + j + 32 * i);
            a.x = fmaf(ww.x, x.x, a.x); a.y = fmaf(ww.y, x.y, a.y);
            a.z = fmaf(ww.z, x.z, a.z); a.w = fmaf(ww.w, x.w, a.w);
        }
        float acc = warp_sum((a.x + a.y) + (a.z + a.w));
        if (j == 0) out[row] = acc + bo[row];
    }

    // ============ counter self-reset (last finisher) =====================
    __syncthreads();
    if (t == 0) {
        __threadfence();
        if (atomicAdd(&g_ctr[6], 1u) == NB - 1) {
            #pragma unroll
            for (int i = 0; i < 7; i++) g_ctr[i] = 0;
            __threadfence();
        }
    }
}

extern "C" void kernel_launch(void* const* d_in, const int* in_sizes, int n_in,
                              void* d_out, int out_size) {
    const float* x   = (const float*)d_in[0];   // [L, E]
    const float* Win = (const float*)d_in[1];   // [3E, E]
    const float* bin = (const float*)d_in[2];   // [3E]
    const float* Wo  = (const float*)d_in[3];   // [E, E]
    const float* bo  = (const float*)d_in[4];   // [E]
    float* out = (float*)d_out;

    cudaFuncSetAttribute(k_mega, cudaFuncAttributeMaxDynamicSharedMemorySize,
                         (int)sizeof(FSmem));

    k_mega<<<NB, 256, sizeof(FSmem)>>>((const float4*)x, (const float4*)Win,
                                       bin, (const float4*)Wo, bo, out);
}